// round 7
// baseline (speedup 1.0000x reference)
#include <cuda_runtime.h>
#include <cuda_bf16.h>
#include <cstdint>

// ---------------------------------------------------------------------------
// Problem constants
// ---------------------------------------------------------------------------
#define NN 100000   // nodes
#define NE 800000   // edges
#define NBLK 98     // ceil(NN/1024) for scan

// ---------------------------------------------------------------------------
// Device-global scratch
// ---------------------------------------------------------------------------
__device__ int   g_cnt[NN];
__device__ int   g_fill[NN];
__device__ int   g_rowptr[NN + 1];
__device__ int   g_bsum[128];
__device__ int   g_csrsrc[NE];
__device__ float g_dinv[NN];
__device__ __align__(16) float g_bufA[(size_t)NN * 256];   // GEMM out / agg in
__device__ __align__(16) float g_bufB[(size_t)NN * 256];   // agg out / apply in
__device__ __align__(16) int8_t g_a8h[(size_t)NN * 256];   // A hi limb
__device__ __align__(16) int8_t g_a8l[(size_t)NN * 256];   // A lo limb
__device__ float        g_S[2];      // LN sum, sumsq
__device__ unsigned int g_U[2];      // LN min/max (order-encoded)
__device__ float        g_prm[2];    // LN mean, invstd
__device__ unsigned int g_maxbits[8];  // abs-max bits: [0..3]=W1..W4, [4]=x
__device__ float g_sW[4], g_isW[4];  // weight scales
__device__ float g_sA[4], g_isA[4];  // activation scales per layer input

// Transposed ([n][k]) int8 hi/lo weight images
__device__ __align__(16) int8_t g_w1h[256 * 256], g_w1l[256 * 256];
__device__ __align__(16) int8_t g_w2h[256 * 256], g_w2l[256 * 256];
__device__ __align__(16) int8_t g_w3h[256 * 256], g_w3l[256 * 256];
__device__ __align__(16) int8_t g_w4h[128 * 256], g_w4l[128 * 256];

static __device__ __forceinline__ uint32_t smem_to_u32(const void* p) {
    uint32_t a;
    asm("{ .reg .u64 t; cvta.to.shared.u64 t, %1; cvt.u32.u64 %0, t; }" : "=r"(a) : "l"(p));
    return a;
}

#define LDMX4(r0, r1, r2, r3, addr) \
    asm volatile("ldmatrix.sync.aligned.m8n8.x4.shared.b16 {%0,%1,%2,%3}, [%4];" \
                 : "=r"(r0), "=r"(r1), "=r"(r2), "=r"(r3) : "r"(addr))

// int8 k32 MMA, s32 accumulate. Fragment byte layout identical to bf16 k16.
#define MMAS8(d, a, b) \
    asm volatile("mma.sync.aligned.m16n8k32.row.col.s32.s8.s8.s32 " \
                 "{%0,%1,%2,%3}, {%4,%5,%6,%7}, {%8,%9}, {%0,%1,%2,%3};" \
                 : "+r"((d)[0]), "+r"((d)[1]), "+r"((d)[2]), "+r"((d)[3]) \
                 : "r"((a)[0]), "r"((a)[1]), "r"((a)[2]), "r"((a)[3]), \
                   "r"((b)[0]), "r"((b)[1]))

#define CP_ASYNC16(saddr, gptr) \
    asm volatile("cp.async.cg.shared.global [%0], [%1], 16;" :: "r"(saddr), "l"(gptr))
#define CP_COMMIT() asm volatile("cp.async.commit_group;")
#define CP_WAIT1()  asm volatile("cp.async.wait_group 1;")
#define CP_WAIT0()  asm volatile("cp.async.wait_group 0;")

// order-preserving float<->uint encoding (for signed min/max atomics)
static __device__ __forceinline__ unsigned int fenc(float f) {
    unsigned int u = __float_as_uint(f);
    return (u & 0x80000000u) ? ~u : (u | 0x80000000u);
}
static __device__ __forceinline__ float fdec(unsigned int u) {
    return (u & 0x80000000u) ? __uint_as_float(u & 0x7FFFFFFFu) : __uint_as_float(~u);
}

// quantize fp32 -> (hi, lo) s8 limbs given inverse scale
static __device__ __forceinline__ void quant2(float v, float isa, int& h, int& l) {
    int q = __float2int_rn(v * isa);
    q = q > 32512 ? 32512 : (q < -32512 ? -32512 : q);
    h = (q + 128) >> 8;
    l = q - (h << 8);
}

// ---------------------------------------------------------------------------
// CSR build (unchanged)
// ---------------------------------------------------------------------------
__global__ void k_zero_counts() {
    int i = blockIdx.x * blockDim.x + threadIdx.x;
    if (i < NN) { g_cnt[i] = 0; g_fill[i] = 0; }
    if (i < 8) g_maxbits[i] = 0u;
}
__global__ void k_degree(const int* __restrict__ dst) {
    int e = blockIdx.x * blockDim.x + threadIdx.x;
    if (e < NE) atomicAdd(&g_cnt[dst[e]], 1);
}
__global__ void k_dinv() {
    int v = blockIdx.x * blockDim.x + threadIdx.x;
    if (v < NN) g_dinv[v] = rsqrtf((float)g_cnt[v] + 1.0f);
}
__global__ void k_scan1() {
    __shared__ int s[1024];
    int t = threadIdx.x;
    int i = blockIdx.x * 1024 + t;
    int v = (i < NN) ? g_cnt[i] : 0;
    s[t] = v;
    __syncthreads();
    for (int off = 1; off < 1024; off <<= 1) {
        int add = (t >= off) ? s[t - off] : 0;
        __syncthreads();
        s[t] += add;
        __syncthreads();
    }
    if (i < NN) g_rowptr[i] = s[t] - v;
    if (t == 1023) g_bsum[blockIdx.x] = s[1023];
}
__global__ void k_scan2() {
    int run = 0;
    for (int b = 0; b < NBLK; b++) { int x = g_bsum[b]; g_bsum[b] = run; run += x; }
    g_rowptr[NN] = run;
}
__global__ void k_scan3() {
    int i = blockIdx.x * blockDim.x + threadIdx.x;
    if (i < NN) g_rowptr[i] += g_bsum[i >> 10];
}
__global__ void k_scatter(const int* __restrict__ src, const int* __restrict__ dst) {
    int e = blockIdx.x * blockDim.x + threadIdx.x;
    if (e < NE) {
        int d = dst[e];
        int pos = g_rowptr[d] + atomicAdd(&g_fill[d], 1);
        g_csrsrc[pos] = src[e];
    }
}

// ---------------------------------------------------------------------------
// Abs-max reduction (non-negative bits -> plain uint atomicMax valid)
// ---------------------------------------------------------------------------
__global__ void k_absmax(const float4* __restrict__ p, int n4, int slot) {
    float m = 0.f;
    for (int i = blockIdx.x * blockDim.x + threadIdx.x; i < n4;
         i += gridDim.x * blockDim.x) {
        float4 v = p[i];
        m = fmaxf(m, fmaxf(fmaxf(fabsf(v.x), fabsf(v.y)),
                           fmaxf(fabsf(v.z), fabsf(v.w))));
    }
#pragma unroll
    for (int o = 16; o > 0; o >>= 1) m = fmaxf(m, __shfl_down_sync(0xffffffffu, m, o));
    __shared__ float sm[8];
    int wid = threadIdx.x >> 5, lane = threadIdx.x & 31;
    if (lane == 0) sm[wid] = m;
    __syncthreads();
    if (threadIdx.x == 0) {
        float r = sm[0];
        for (int w = 1; w < (int)(blockDim.x >> 5); w++) r = fmaxf(r, sm[w]);
        atomicMax(&g_maxbits[slot], __float_as_uint(r));
    }
}

__global__ void k_scales() {
    for (int i = 0; i < 4; i++) {
        float f = __uint_as_float(g_maxbits[i]);
        float s = fmaxf(f, 1e-30f) / 32512.f;
        g_sW[i] = s; g_isW[i] = 1.f / s;
    }
    float fx = __uint_as_float(g_maxbits[4]);
    float s = fmaxf(fx, 1e-30f) / 32512.f;
    g_sA[0] = s; g_isA[0] = 1.f / s;
}

// ---------------------------------------------------------------------------
// Weight pack: W[k][n] fp32 -> transposed [n][k] int8 hi/lo limbs
// ---------------------------------------------------------------------------
__global__ void k_wpack(const float* __restrict__ W, int8_t* __restrict__ hi,
                        int8_t* __restrict__ lo, int Nc, int li) {
    int i = blockIdx.x * blockDim.x + threadIdx.x;
    if (i >= 256 * Nc) return;
    int k = i / Nc, n = i - k * Nc;
    float isw = g_isW[li];
    int h, l;
    quant2(W[i], isw, h, l);
    int o = n * 256 + k;
    hi[o] = (int8_t)h;
    lo[o] = (int8_t)l;
}

// X pack (layer-1 input)
__global__ void k_xpack(const float* __restrict__ x,
                        int8_t* __restrict__ ah, int8_t* __restrict__ al) {
    int i4 = blockIdx.x * blockDim.x + threadIdx.x;  // NN*64 total
    float isa = g_isA[0];
    float4 v = ((const float4*)x)[i4];
    int h0, l0, h1, l1, h2, l2, h3, l3;
    quant2(v.x, isa, h0, l0); quant2(v.y, isa, h1, l1);
    quant2(v.z, isa, h2, l2); quant2(v.w, isa, h3, l3);
    ((uchar4*)ah)[i4] = make_uchar4((unsigned char)h0, (unsigned char)h1,
                                    (unsigned char)h2, (unsigned char)h3);
    ((uchar4*)al)[i4] = make_uchar4((unsigned char)l0, (unsigned char)l1,
                                    (unsigned char)l2, (unsigned char)l3);
}

// ---------------------------------------------------------------------------
// int8-split MMA GEMM: C[M,NC] = sA*sW * (65536*Shh + 256*(Shl+Slh))
// CTA 128x64, 8 warps (4m x 2n), 4 K-chunks of 64 bytes, 2-stage cp.async.
// Fragment addressing identical to the proven bf16 kernel (s8k32 == bf16k16).
// ---------------------------------------------------------------------------
#define ST_AH 0
#define ST_AL 10240
#define ST_WH 20480
#define ST_WL 25600
#define STAGE_SZ 30720
#define GEMM_SMEM (2 * STAGE_SZ)

template <int NC>
__global__ void __launch_bounds__(256, 2)
k_gemm_i8(const int8_t* __restrict__ Ah, const int8_t* __restrict__ Al,
          const int8_t* __restrict__ Wh, const int8_t* __restrict__ Wl,
          const float* __restrict__ sAp, const float* __restrict__ sWp,
          float* __restrict__ C, int M)
{
    extern __shared__ __align__(16) char smem[];
    uint32_t sb = smem_to_u32(smem);

    int tid = threadIdx.x;
    int wid = tid >> 5, lane = tid & 31;
    int m0 = blockIdx.y * 128;
    int bn = blockIdx.x * 64;
    int warp_m = wid & 3;
    int warp_n = wid >> 2;

    float scale = sAp[0] * sWp[0];

    int accA[2][4][4], accB[2][4][4];
#pragma unroll
    for (int i = 0; i < 2; i++)
#pragma unroll
        for (int j = 0; j < 4; j++)
#pragma unroll
            for (int q = 0; q < 4; q++) { accA[i][j][q] = 0; accB[i][j][q] = 0; }

    // ---- copy mappings (rows are 256 bytes) ----
    int arow = tid >> 1, ahalf = tid & 1;
    int gra = m0 + arow; if (gra > M - 1) gra = M - 1;
    const char* gAh = (const char*)(Ah + (size_t)gra * 256) + ahalf * 32;
    const char* gAl = (const char*)(Al + (size_t)gra * 256) + ahalf * 32;
    uint32_t sAoff = (uint32_t)arow * 80u + (uint32_t)ahalf * 32u;
    int wr = tid >> 2, ws = tid & 3;
    const char* gWh = (const char*)(Wh + (size_t)(bn + wr) * 256) + ws * 16;
    const char* gWl = (const char*)(Wl + (size_t)(bn + wr) * 256) + ws * 16;
    uint32_t sWoff = (uint32_t)wr * 80u + (uint32_t)ws * 16u;

    // ---- ldmatrix per-thread relative offsets (same as bf16 kernel) ----
    uint32_t aRel[2], lRel[2];
#pragma unroll
    for (int i = 0; i < 2; i++) {
        uint32_t row = warp_m * 32 + i * 16 + (lane & 15);
        uint32_t col = ((lane >> 4) & 1) * 16;
        aRel[i] = ST_AH + row * 80 + col;
        lRel[i] = ST_AL + row * 80 + col;
    }
    uint32_t bRel[2], blRel[2];
#pragma unroll
    for (int p = 0; p < 2; p++) {
        uint32_t row = warp_n * 32 + p * 16 + (lane & 7) + ((lane >> 4) & 1) * 8;
        uint32_t col = ((lane >> 3) & 1) * 16;
        bRel[p]  = ST_WH + row * 80 + col;
        blRel[p] = ST_WL + row * 80 + col;
    }

    auto issue = [&](int kc, int stg) {
        uint32_t base = sb + stg * STAGE_SZ;
        int gofs = kc * 64;
        CP_ASYNC16(base + ST_AH + sAoff,      gAh + gofs);
        CP_ASYNC16(base + ST_AH + sAoff + 16, gAh + gofs + 16);
        CP_ASYNC16(base + ST_AL + sAoff,      gAl + gofs);
        CP_ASYNC16(base + ST_AL + sAoff + 16, gAl + gofs + 16);
        CP_ASYNC16(base + ST_WH + sWoff,      gWh + gofs);
        CP_ASYNC16(base + ST_WL + sWoff,      gWl + gofs);
    };

    issue(0, 0);
    CP_COMMIT();

    for (int kc = 0; kc < 4; kc++) {
        int cur = kc & 1;
        if (kc < 3) {
            issue(kc + 1, cur ^ 1);
            CP_COMMIT();
            CP_WAIT1();
        } else {
            CP_WAIT0();
        }
        __syncthreads();

        uint32_t base = sb + cur * STAGE_SZ;
#pragma unroll
        for (int s = 0; s < 2; s++) {      // each s = 32 bytes = k32
            uint32_t ah[2][4], al[2][4];
            uint32_t wh[4][2], wl[4][2];
#pragma unroll
            for (int i = 0; i < 2; i++) {
                LDMX4(ah[i][0], ah[i][1], ah[i][2], ah[i][3], base + aRel[i] + s * 32);
                LDMX4(al[i][0], al[i][1], al[i][2], al[i][3], base + lRel[i] + s * 32);
            }
#pragma unroll
            for (int p = 0; p < 2; p++) {
                LDMX4(wh[2 * p][0], wh[2 * p][1], wh[2 * p + 1][0], wh[2 * p + 1][1],
                      base + bRel[p] + s * 32);
                LDMX4(wl[2 * p][0], wl[2 * p][1], wl[2 * p + 1][0], wl[2 * p + 1][1],
                      base + blRel[p] + s * 32);
            }
#pragma unroll
            for (int i = 0; i < 2; i++)
#pragma unroll
                for (int j = 0; j < 4; j++) {
                    MMAS8(accA[i][j], ah[i], wh[j]);   // hi*hi  (scale 65536)
                    MMAS8(accB[i][j], ah[i], wl[j]);   // hi*lo  (scale 256)
                    MMAS8(accB[i][j], al[i], wh[j]);   // lo*hi  (scale 256)
                }
        }
        __syncthreads();
    }

    // ---- epilogue: combine limbs, stage fp32 tile, coalesced store ----
    float* otile = (float*)smem;
#pragma unroll
    for (int i = 0; i < 2; i++)
#pragma unroll
        for (int j = 0; j < 4; j++) {
            int r0 = warp_m * 32 + i * 16 + (lane >> 2);
            int c0 = warp_n * 32 + j * 8 + (lane & 3) * 2;
            float v0 = (65536.f * (float)accA[i][j][0] + 256.f * (float)accB[i][j][0]) * scale;
            float v1 = (65536.f * (float)accA[i][j][1] + 256.f * (float)accB[i][j][1]) * scale;
            float v2 = (65536.f * (float)accA[i][j][2] + 256.f * (float)accB[i][j][2]) * scale;
            float v3 = (65536.f * (float)accA[i][j][3] + 256.f * (float)accB[i][j][3]) * scale;
            *(float2*)(otile + r0 * 68 + c0)       = make_float2(v0, v1);
            *(float2*)(otile + (r0 + 8) * 68 + c0) = make_float2(v2, v3);
        }
    __syncthreads();

#pragma unroll
    for (int it = 0; it < 8; it++) {
        int idx = tid + it * 256;
        int row = idx >> 4;
        int c4 = idx & 15;
        int gr = m0 + row;
        if (gr < M) {
            float4 v = *(float4*)(otile + row * 68 + c4 * 4);
            *(float4*)(C + (size_t)gr * NC + bn + c4 * 4) = v;
        }
    }
}

// ---------------------------------------------------------------------------
// Aggregation (adds min/max tracking for quantization bound)
// ---------------------------------------------------------------------------
__global__ void k_agg256(const float* __restrict__ h, const float* __restrict__ bias,
                         float* __restrict__ out, int stats)
{
    int warp = threadIdx.x >> 5, lane = threadIdx.x & 31;
    int v = blockIdx.x * 8 + warp;

    float4 a0 = make_float4(0.f, 0.f, 0.f, 0.f);
    float4 a1 = make_float4(0.f, 0.f, 0.f, 0.f);

    int beg = g_rowptr[v], end = g_rowptr[v + 1];
    int nb = end - beg;
    for (int base = 0; base < nb; base += 32) {
        int rem = nb - base;
        int cnt = rem < 32 ? rem : 32;
        int idx = base + lane;
        int sl = (idx < nb) ? g_csrsrc[beg + idx] : 0;
        float wl = (idx < nb) ? g_dinv[sl] : 0.f;
        for (int j = 0; j < cnt; j++) {
            int   s = __shfl_sync(0xffffffffu, sl, j);
            float w = __shfl_sync(0xffffffffu, wl, j);
            const float4* rr = (const float4*)(h + (size_t)s * 256);
            float4 f0 = rr[lane], f1 = rr[lane + 32];
            a0.x += w * f0.x; a0.y += w * f0.y; a0.z += w * f0.z; a0.w += w * f0.w;
            a1.x += w * f1.x; a1.y += w * f1.y; a1.z += w * f1.z; a1.w += w * f1.w;
        }
    }
    float dv = g_dinv[v];
    {
        const float4* rr = (const float4*)(h + (size_t)v * 256);
        float4 f0 = rr[lane], f1 = rr[lane + 32];
        a0.x += dv * f0.x; a0.y += dv * f0.y; a0.z += dv * f0.z; a0.w += dv * f0.w;
        a1.x += dv * f1.x; a1.y += dv * f1.y; a1.z += dv * f1.z; a1.w += dv * f1.w;
    }
    const float4* bb = (const float4*)bias;
    float4 b0 = bb[lane], b1 = bb[lane + 32];
    float4 r0, r1;
    r0.x = a0.x * dv + b0.x; r0.y = a0.y * dv + b0.y;
    r0.z = a0.z * dv + b0.z; r0.w = a0.w * dv + b0.w;
    r1.x = a1.x * dv + b1.x; r1.y = a1.y * dv + b1.y;
    r1.z = a1.z * dv + b1.z; r1.w = a1.w * dv + b1.w;

    float4* op = (float4*)(out + (size_t)v * 256);
    op[lane] = r0; op[lane + 32] = r1;

    if (stats) {
        float lsum = r0.x + r0.y + r0.z + r0.w + r1.x + r1.y + r1.z + r1.w;
        float lsq  = r0.x*r0.x + r0.y*r0.y + r0.z*r0.z + r0.w*r0.w
                   + r1.x*r1.x + r1.y*r1.y + r1.z*r1.z + r1.w*r1.w;
        float lmn = fminf(fminf(fminf(r0.x, r0.y), fminf(r0.z, r0.w)),
                          fminf(fminf(r1.x, r1.y), fminf(r1.z, r1.w)));
        float lmx = fmaxf(fmaxf(fmaxf(r0.x, r0.y), fmaxf(r0.z, r0.w)),
                          fmaxf(fmaxf(r1.x, r1.y), fmaxf(r1.z, r1.w)));
#pragma unroll
        for (int off = 16; off > 0; off >>= 1) {
            lsum += __shfl_down_sync(0xffffffffu, lsum, off);
            lsq  += __shfl_down_sync(0xffffffffu, lsq,  off);
            lmn = fminf(lmn, __shfl_down_sync(0xffffffffu, lmn, off));
            lmx = fmaxf(lmx, __shfl_down_sync(0xffffffffu, lmx, off));
        }
        __shared__ float ss[8], sq[8], smn[8], smx[8];
        if (lane == 0) { ss[warp] = lsum; sq[warp] = lsq; smn[warp] = lmn; smx[warp] = lmx; }
        __syncthreads();
        if (threadIdx.x == 0) {
            float S = 0.f, Q = 0.f, MN = smn[0], MX = smx[0];
#pragma unroll
            for (int w = 0; w < 8; w++) {
                S += ss[w]; Q += sq[w];
                MN = fminf(MN, smn[w]); MX = fmaxf(MX, smx[w]);
            }
            atomicAdd(&g_S[0], S);
            atomicAdd(&g_S[1], Q);
            atomicMin(&g_U[0], fenc(MN));
            atomicMax(&g_U[1], fenc(MX));
        }
    }
}

__global__ void k_agg128(const float* __restrict__ h, const float* __restrict__ bias,
                         float* __restrict__ out)
{
    int warp = threadIdx.x >> 5, lane = threadIdx.x & 31;
    int v = blockIdx.x * 8 + warp;

    float4 a0 = make_float4(0.f, 0.f, 0.f, 0.f);
    int beg = g_rowptr[v], end = g_rowptr[v + 1];
    int nb = end - beg;
    for (int base = 0; base < nb; base += 32) {
        int rem = nb - base;
        int cnt = rem < 32 ? rem : 32;
        int idx = base + lane;
        int sl = (idx < nb) ? g_csrsrc[beg + idx] : 0;
        float wl = (idx < nb) ? g_dinv[sl] : 0.f;
        for (int j = 0; j < cnt; j++) {
            int   s = __shfl_sync(0xffffffffu, sl, j);
            float w = __shfl_sync(0xffffffffu, wl, j);
            const float4* rr = (const float4*)(h + (size_t)s * 128);
            float4 f0 = rr[lane];
            a0.x += w * f0.x; a0.y += w * f0.y; a0.z += w * f0.z; a0.w += w * f0.w;
        }
    }
    float dv = g_dinv[v];
    {
        const float4* rr = (const float4*)(h + (size_t)v * 128);
        float4 f0 = rr[lane];
        a0.x += dv * f0.x; a0.y += dv * f0.y; a0.z += dv * f0.z; a0.w += dv * f0.w;
    }
    const float4* bb = (const float4*)bias;
    float4 b0 = bb[lane];
    float4 r0;
    r0.x = a0.x * dv + b0.x; r0.y = a0.y * dv + b0.y;
    r0.z = a0.z * dv + b0.z; r0.w = a0.w * dv + b0.w;
    ((float4*)(out + (size_t)v * 128))[lane] = r0;
}

// ---------------------------------------------------------------------------
// LayerNorm(graph) + quantization-scale derivation
// ---------------------------------------------------------------------------
__global__ void k_zeroS() {
    g_S[0] = 0.f; g_S[1] = 0.f;
    g_U[0] = 0xFFFFFFFFu; g_U[1] = 0u;
}

// 256 threads: reduce max|gamma|, max|beta|; finalize LN params and A-scale.
__global__ void k_lnfin_q(const float* __restrict__ gma,
                          const float* __restrict__ bta, int li) {
    __shared__ float sg[256], sbb[256];
    int t = threadIdx.x;
    sg[t] = fabsf(gma[t]);
    sbb[t] = fabsf(bta[t]);
    __syncthreads();
    for (int o = 128; o > 0; o >>= 1) {
        if (t < o) {
            sg[t] = fmaxf(sg[t], sg[t + o]);
            sbb[t] = fmaxf(sbb[t], sbb[t + o]);
        }
        __syncthreads();
    }
    if (t == 0) {
        float cnt = (float)NN * 256.0f;
        float mean = g_S[0] / cnt;
        float var  = g_S[1] / cnt - mean * mean;
        var = fmaxf(var, 0.f);
        float invstd = 1.0f / (sqrtf(var) + 1e-5f);
        float mn = fdec(g_U[0]), mx = fdec(g_U[1]);
        float zmax = fmaxf(mx - mean, mean - mn) * invstd;
        float ymax = zmax * sg[0] + sbb[0];
        float s = fmaxf(ymax, 1e-20f) / 32512.f;
        g_prm[0] = mean;
        g_prm[1] = invstd;
        g_sA[li] = s;
        g_isA[li] = 1.f / s;
    }
}

// y = lrelu((x-mean)*invstd*gamma + beta), emitted as int8 hi/lo limbs
__global__ void k_apply_q(const float* __restrict__ buf,
                          const float* __restrict__ gma,
                          const float* __restrict__ bta,
                          int li,
                          int8_t* __restrict__ ah, int8_t* __restrict__ al)
{
    int i4 = blockIdx.x * blockDim.x + threadIdx.x;  // NN*64 total
    float mean = g_prm[0], scale = g_prm[1];
    float isa = g_isA[li];
    int c4 = i4 & 63;
    float4 g = ((const float4*)gma)[c4];
    float4 b = ((const float4*)bta)[c4];
    float4 v = ((const float4*)buf)[i4];
    v.x = (v.x - mean) * scale * g.x + b.x;
    v.y = (v.y - mean) * scale * g.y + b.y;
    v.z = (v.z - mean) * scale * g.z + b.z;
    v.w = (v.w - mean) * scale * g.w + b.w;
    v.x = v.x > 0.f ? v.x : 0.01f * v.x;
    v.y = v.y > 0.f ? v.y : 0.01f * v.y;
    v.z = v.z > 0.f ? v.z : 0.01f * v.z;
    v.w = v.w > 0.f ? v.w : 0.01f * v.w;
    int h0, l0, h1, l1, h2, l2, h3, l3;
    quant2(v.x, isa, h0, l0); quant2(v.y, isa, h1, l1);
    quant2(v.z, isa, h2, l2); quant2(v.w, isa, h3, l3);
    ((uchar4*)ah)[i4] = make_uchar4((unsigned char)h0, (unsigned char)h1,
                                    (unsigned char)h2, (unsigned char)h3);
    ((uchar4*)al)[i4] = make_uchar4((unsigned char)l0, (unsigned char)l1,
                                    (unsigned char)l2, (unsigned char)l3);
}

// ---------------------------------------------------------------------------
// Host launcher
// ---------------------------------------------------------------------------
extern "C" void kernel_launch(void* const* d_in, const int* in_sizes, int n_in,
                              void* d_out, int out_size)
{
    const float* x   = (const float*)d_in[0];
    const int*   ei  = (const int*)d_in[1];
    const int*   src = ei;
    const int*   dst = ei + NE;
    const float* W1 = (const float*)d_in[2];
    const float* b1 = (const float*)d_in[3];
    const float* g1 = (const float*)d_in[4];
    const float* e1 = (const float*)d_in[5];
    const float* W2 = (const float*)d_in[6];
    const float* b2 = (const float*)d_in[7];
    const float* g2 = (const float*)d_in[8];
    const float* e2 = (const float*)d_in[9];
    const float* W3 = (const float*)d_in[10];
    const float* b3 = (const float*)d_in[11];
    const float* g3 = (const float*)d_in[12];
    const float* e3 = (const float*)d_in[13];
    const float* W4 = (const float*)d_in[14];
    const float* b4 = (const float*)d_in[15];
    float* out = (float*)d_out;

    float *bufA = nullptr, *bufB = nullptr;
    cudaGetSymbolAddress((void**)&bufA, g_bufA);
    cudaGetSymbolAddress((void**)&bufB, g_bufB);
    int8_t *a8h, *a8l;
    cudaGetSymbolAddress((void**)&a8h, g_a8h);
    cudaGetSymbolAddress((void**)&a8l, g_a8l);
    int8_t *w1h, *w1l, *w2h, *w2l, *w3h, *w3l, *w4h, *w4l;
    cudaGetSymbolAddress((void**)&w1h, g_w1h); cudaGetSymbolAddress((void**)&w1l, g_w1l);
    cudaGetSymbolAddress((void**)&w2h, g_w2h); cudaGetSymbolAddress((void**)&w2l, g_w2l);
    cudaGetSymbolAddress((void**)&w3h, g_w3h); cudaGetSymbolAddress((void**)&w3l, g_w3l);
    cudaGetSymbolAddress((void**)&w4h, g_w4h); cudaGetSymbolAddress((void**)&w4l, g_w4l);
    float *sA, *sW;
    cudaGetSymbolAddress((void**)&sA, g_sA);
    cudaGetSymbolAddress((void**)&sW, g_sW);

    static bool attr_done = false;
    if (!attr_done) {
        cudaFuncSetAttribute(k_gemm_i8<256>, cudaFuncAttributeMaxDynamicSharedMemorySize, GEMM_SMEM);
        cudaFuncSetAttribute(k_gemm_i8<128>, cudaFuncAttributeMaxDynamicSharedMemorySize, GEMM_SMEM);
        attr_done = true;
    }

    const int T = 256;
    // ---- CSR build (also zeroes max slots) ----
    k_zero_counts<<<(NN + T - 1) / T, T>>>();
    k_degree<<<(NE + T - 1) / T, T>>>(dst);
    k_dinv<<<(NN + T - 1) / T, T>>>();
    k_scan1<<<NBLK, 1024>>>();
    k_scan2<<<1, 1>>>();
    k_scan3<<<(NN + T - 1) / T, T>>>();
    k_scatter<<<(NE + T - 1) / T, T>>>(src, dst);

    // ---- abs-max + scales + packing ----
    k_absmax<<<64, 256>>>((const float4*)W1, 256 * 64, 0);
    k_absmax<<<64, 256>>>((const float4*)W2, 256 * 64, 1);
    k_absmax<<<64, 256>>>((const float4*)W3, 256 * 64, 2);
    k_absmax<<<32, 256>>>((const float4*)W4, 128 * 64, 3);
    k_absmax<<<2048, 256>>>((const float4*)x, NN * 64, 4);
    k_scales<<<1, 1>>>();
    k_wpack<<<(256 * 256 + T - 1) / T, T>>>(W1, w1h, w1l, 256, 0);
    k_wpack<<<(256 * 256 + T - 1) / T, T>>>(W2, w2h, w2l, 256, 1);
    k_wpack<<<(256 * 256 + T - 1) / T, T>>>(W3, w3h, w3l, 256, 2);
    k_wpack<<<(256 * 128 + T - 1) / T, T>>>(W4, w4h, w4l, 128, 3);

    dim3 grid256(4, (NN + 127) / 128);    // x = n-block, y = m-block
    dim3 grid128(2, (NN + 127) / 128);
    int aggBlocks = NN / 8;               // 12500
    int vecBlocks = (NN * 64) / T;        // 25000

    k_xpack<<<vecBlocks, T>>>(x, a8h, a8l);

    // ---- layer 1 ----
    k_gemm_i8<256><<<grid256, 256, GEMM_SMEM>>>(a8h, a8l, w1h, w1l, sA + 0, sW + 0, bufA, NN);
    k_zeroS<<<1, 1>>>();
    k_agg256<<<aggBlocks, 256>>>(bufA, b1, bufB, 1);
    k_lnfin_q<<<1, 256>>>(g1, e1, 1);
    k_apply_q<<<vecBlocks, T>>>(bufB, g1, e1, 1, a8h, a8l);

    // ---- layer 2 ----
    k_gemm_i8<256><<<grid256, 256, GEMM_SMEM>>>(a8h, a8l, w2h, w2l, sA + 1, sW + 1, bufA, NN);
    k_zeroS<<<1, 1>>>();
    k_agg256<<<aggBlocks, 256>>>(bufA, b2, bufB, 1);
    k_lnfin_q<<<1, 256>>>(g2, e2, 2);
    k_apply_q<<<vecBlocks, T>>>(bufB, g2, e2, 2, a8h, a8l);

    // ---- layer 3 ----
    k_gemm_i8<256><<<grid256, 256, GEMM_SMEM>>>(a8h, a8l, w3h, w3l, sA + 2, sW + 2, bufA, NN);
    k_zeroS<<<1, 1>>>();
    k_agg256<<<aggBlocks, 256>>>(bufA, b3, bufB, 1);
    k_lnfin_q<<<1, 256>>>(g3, e3, 3);
    k_apply_q<<<vecBlocks, T>>>(bufB, g3, e3, 3, a8h, a8l);

    // ---- layer 4 (D=128, no LN) ----
    k_gemm_i8<128><<<grid128, 256, GEMM_SMEM>>>(a8h, a8l, w4h, w4l, sA + 3, sW + 3, bufA, NN);
    k_agg128<<<aggBlocks, 256>>>(bufA, b4, out);
}

// round 8
// speedup vs baseline: 1.4918x; 1.4918x over previous
#include <cuda_runtime.h>
#include <cuda_bf16.h>
#include <cstdint>

// ---------------------------------------------------------------------------
// Problem constants
// ---------------------------------------------------------------------------
#define NN 100000   // nodes
#define NE 800000   // edges
#define NBLK 98     // ceil(NN/1024) for scan

// ---------------------------------------------------------------------------
// Device-global scratch
// ---------------------------------------------------------------------------
__device__ int   g_cnt[NN];
__device__ int   g_fill[NN];
__device__ int   g_rowptr[NN + 1];
__device__ int   g_bsum[128];
__device__ int   g_csrsrc[NE];
__device__ float g_dinv[NN];
__device__ __align__(16) float g_bufA[(size_t)NN * 256];   // GEMM out / agg in
__device__ __align__(16) float g_bufB[(size_t)NN * 256];   // agg out / apply in
__device__ __align__(16) __nv_bfloat16 g_ah[(size_t)NN * 256];  // GEMM A hi
__device__ __align__(16) __nv_bfloat16 g_al[(size_t)NN * 256];  // GEMM A lo
__device__ float g_S[2];     // LN sum, sumsq

// Transposed ([n][k]) bf16 hi/lo weight images
__device__ __align__(16) __nv_bfloat16 g_w1h[256 * 256], g_w1l[256 * 256];
__device__ __align__(16) __nv_bfloat16 g_w2h[256 * 256], g_w2l[256 * 256];
__device__ __align__(16) __nv_bfloat16 g_w3h[256 * 256], g_w3l[256 * 256];
__device__ __align__(16) __nv_bfloat16 g_w4h[128 * 256], g_w4l[128 * 256];

static __device__ __forceinline__ uint32_t smem_to_u32(const void* p) {
    uint32_t a;
    asm("{ .reg .u64 t; cvta.to.shared.u64 t, %1; cvt.u32.u64 %0, t; }" : "=r"(a) : "l"(p));
    return a;
}

#define LDMX4(r0, r1, r2, r3, addr) \
    asm volatile("ldmatrix.sync.aligned.m8n8.x4.shared.b16 {%0,%1,%2,%3}, [%4];" \
                 : "=r"(r0), "=r"(r1), "=r"(r2), "=r"(r3) : "r"(addr))

#define MMA16816(d, a, b) \
    asm volatile("mma.sync.aligned.m16n8k16.row.col.f32.bf16.bf16.f32 " \
                 "{%0,%1,%2,%3}, {%4,%5,%6,%7}, {%8,%9}, {%0,%1,%2,%3};" \
                 : "+f"((d)[0]), "+f"((d)[1]), "+f"((d)[2]), "+f"((d)[3]) \
                 : "r"((a)[0]), "r"((a)[1]), "r"((a)[2]), "r"((a)[3]), \
                   "r"((b)[0]), "r"((b)[1]))

#define CP_ASYNC16(saddr, gptr) \
    asm volatile("cp.async.cg.shared.global [%0], [%1], 16;" :: "r"(saddr), "l"(gptr))
#define CP_COMMIT() asm volatile("cp.async.commit_group;")
#define CP_WAIT1()  asm volatile("cp.async.wait_group 1;")
#define CP_WAIT0()  asm volatile("cp.async.wait_group 0;")

static __device__ __forceinline__ uint32_t packbf2(float a, float b) {
    __nv_bfloat162 t = __floats2bfloat162_rn(a, b);
    return *reinterpret_cast<uint32_t*>(&t);
}

// split a float4 into bf16-hi (uint2) and bf16-lo (uint2)
static __device__ __forceinline__ void split4(float4 v, uint2& hv, uint2& lv) {
    __nv_bfloat16 h0 = __float2bfloat16_rn(v.x), h1 = __float2bfloat16_rn(v.y);
    __nv_bfloat16 h2 = __float2bfloat16_rn(v.z), h3 = __float2bfloat16_rn(v.w);
    float l0 = v.x - __bfloat162float(h0), l1 = v.y - __bfloat162float(h1);
    float l2 = v.z - __bfloat162float(h2), l3 = v.w - __bfloat162float(h3);
    __nv_bfloat162 hh01; hh01.x = h0; hh01.y = h1;
    __nv_bfloat162 hh23; hh23.x = h2; hh23.y = h3;
    hv = make_uint2(*reinterpret_cast<uint32_t*>(&hh01),
                    *reinterpret_cast<uint32_t*>(&hh23));
    lv = make_uint2(packbf2(l0, l1), packbf2(l2, l3));
}

// ---------------------------------------------------------------------------
// CSR build
// ---------------------------------------------------------------------------
__global__ void k_zero_counts() {
    int i = blockIdx.x * blockDim.x + threadIdx.x;
    if (i < NN) { g_cnt[i] = 0; g_fill[i] = 0; }
}
__global__ void k_degree(const int* __restrict__ dst) {
    int e = blockIdx.x * blockDim.x + threadIdx.x;
    if (e < NE) atomicAdd(&g_cnt[dst[e]], 1);
}
__global__ void k_dinv() {
    int v = blockIdx.x * blockDim.x + threadIdx.x;
    if (v < NN) g_dinv[v] = rsqrtf((float)g_cnt[v] + 1.0f);
}
__global__ void k_scan1() {
    __shared__ int s[1024];
    int t = threadIdx.x;
    int i = blockIdx.x * 1024 + t;
    int v = (i < NN) ? g_cnt[i] : 0;
    s[t] = v;
    __syncthreads();
    for (int off = 1; off < 1024; off <<= 1) {
        int add = (t >= off) ? s[t - off] : 0;
        __syncthreads();
        s[t] += add;
        __syncthreads();
    }
    if (i < NN) g_rowptr[i] = s[t] - v;
    if (t == 1023) g_bsum[blockIdx.x] = s[1023];
}
__global__ void k_scan2() {
    int run = 0;
    for (int b = 0; b < NBLK; b++) { int x = g_bsum[b]; g_bsum[b] = run; run += x; }
    g_rowptr[NN] = run;
}
__global__ void k_scan3() {
    int i = blockIdx.x * blockDim.x + threadIdx.x;
    if (i < NN) g_rowptr[i] += g_bsum[i >> 10];
}
__global__ void k_scatter(const int* __restrict__ src, const int* __restrict__ dst) {
    int e = blockIdx.x * blockDim.x + threadIdx.x;
    if (e < NE) {
        int d = dst[e];
        int pos = g_rowptr[d] + atomicAdd(&g_fill[d], 1);
        g_csrsrc[pos] = src[e];
    }
}

// ---------------------------------------------------------------------------
// Weight prep: W[k][n] fp32 -> transposed [n][k] bf16 hi/lo
// ---------------------------------------------------------------------------
__global__ void k_wprep(const float* __restrict__ W, __nv_bfloat16* __restrict__ hi,
                        __nv_bfloat16* __restrict__ lo, int Nc) {
    int i = blockIdx.x * blockDim.x + threadIdx.x;
    if (i >= 256 * Nc) return;
    int k = i / Nc, n = i - k * Nc;
    float w = W[i];
    __nv_bfloat16 h = __float2bfloat16_rn(w);
    float rem = w - __bfloat162float(h);
    __nv_bfloat16 l = __float2bfloat16_rn(rem);
    int o = n * 256 + k;
    hi[o] = h;
    lo[o] = l;
}

// X conversion (layer-1 input): fp32 -> bf16 hi/lo images
__global__ void k_xconv(const float* __restrict__ x,
                        __nv_bfloat16* __restrict__ ah, __nv_bfloat16* __restrict__ al) {
    int i4 = blockIdx.x * blockDim.x + threadIdx.x;  // NN*64 total
    float4 v = ((const float4*)x)[i4];
    uint2 hv, lv;
    split4(v, hv, lv);
    ((uint2*)ah)[i4] = hv;
    ((uint2*)al)[i4] = lv;
}

// ---------------------------------------------------------------------------
// bf16-split HMMA GEMM: C[M,NC] = A[M,256] @ W[256,NC]
// A pre-converted to bf16 hi/lo. CTA 128x64, 8 warps (4m x 2n), BK=32,
// 3-stage cp.async pipeline. Terms ah*wh + ah*wl + al*wh, fp32 accumulate.
// Also zeroes the LN stats accumulator (block 0,0) for the downstream agg.
// ---------------------------------------------------------------------------
#define ST_AH 0
#define ST_AL 10240
#define ST_WH 20480
#define ST_WL 25600
#define STAGE_SZ 30720
#define NSTG 3
#define GEMM_SMEM (NSTG * STAGE_SZ)   // 92160 >= 34816 output staging

template <int NC>
__global__ void __launch_bounds__(256, 2)
k_gemm_mma(const __nv_bfloat16* __restrict__ Ah,
           const __nv_bfloat16* __restrict__ Al,
           const __nv_bfloat16* __restrict__ Whi,
           const __nv_bfloat16* __restrict__ Wlo,
           float* __restrict__ C, int M)
{
    extern __shared__ __align__(16) char smem[];
    uint32_t sb = smem_to_u32(smem);

    int tid = threadIdx.x;
    int wid = tid >> 5, lane = tid & 31;
    int m0 = blockIdx.y * 128;
    int bn = blockIdx.x * 64;
    int warp_m = wid & 3;
    int warp_n = wid >> 2;

    // zero LN stats for the aggregation kernel that follows this GEMM
    if (blockIdx.x == 0 && blockIdx.y == 0 && tid == 0) {
        g_S[0] = 0.f; g_S[1] = 0.f;
    }

    float acc[2][4][4];
#pragma unroll
    for (int i = 0; i < 2; i++)
#pragma unroll
        for (int j = 0; j < 4; j++)
#pragma unroll
            for (int q = 0; q < 4; q++) acc[i][j][q] = 0.f;

    // ---- copy mappings ----
    int arow = tid >> 1, ahalf = tid & 1;
    int gra = m0 + arow; if (gra > M - 1) gra = M - 1;   // clamp (rows unused)
    const char* gAh = (const char*)(Ah + (size_t)gra * 256) + ahalf * 32;
    const char* gAl = (const char*)(Al + (size_t)gra * 256) + ahalf * 32;
    uint32_t sAoff = (uint32_t)arow * 80u + (uint32_t)ahalf * 32u;
    int wr = tid >> 2, ws = tid & 3;
    const char* gWh = (const char*)(Whi + (size_t)(bn + wr) * 256) + ws * 16;
    const char* gWl = (const char*)(Wlo + (size_t)(bn + wr) * 256) + ws * 16;
    uint32_t sWoff = (uint32_t)wr * 80u + (uint32_t)ws * 16u;

    // ---- ldmatrix per-thread relative offsets ----
    uint32_t aRel[2], lRel[2];
#pragma unroll
    for (int i = 0; i < 2; i++) {
        uint32_t row = warp_m * 32 + i * 16 + (lane & 15);
        uint32_t col = ((lane >> 4) & 1) * 16;
        aRel[i] = ST_AH + row * 80 + col;
        lRel[i] = ST_AL + row * 80 + col;
    }
    uint32_t bRel[2], blRel[2];
#pragma unroll
    for (int p = 0; p < 2; p++) {
        uint32_t row = warp_n * 32 + p * 16 + (lane & 7) + ((lane >> 4) & 1) * 8;
        uint32_t col = ((lane >> 3) & 1) * 16;
        bRel[p]  = ST_WH + row * 80 + col;
        blRel[p] = ST_WL + row * 80 + col;
    }

    auto issue = [&](int kc, int stg) {
        uint32_t base = sb + stg * STAGE_SZ;
        int gofs = kc * 64;
        CP_ASYNC16(base + ST_AH + sAoff,      gAh + gofs);
        CP_ASYNC16(base + ST_AH + sAoff + 16, gAh + gofs + 16);
        CP_ASYNC16(base + ST_AL + sAoff,      gAl + gofs);
        CP_ASYNC16(base + ST_AL + sAoff + 16, gAl + gofs + 16);
        CP_ASYNC16(base + ST_WH + sWoff,      gWh + gofs);
        CP_ASYNC16(base + ST_WL + sWoff,      gWl + gofs);
    };

    issue(0, 0); CP_COMMIT();
    issue(1, 1); CP_COMMIT();

    for (int kc = 0; kc < 8; kc++) {
        if (kc < 7) CP_WAIT1(); else CP_WAIT0();
        __syncthreads();
        // prefetch 2 chunks ahead into the stage freed last iteration
        if (kc < 6) {
            issue(kc + 2, (kc + 2) % NSTG);
            CP_COMMIT();
        }

        uint32_t base = sb + (kc % NSTG) * STAGE_SZ;
#pragma unroll
        for (int s = 0; s < 2; s++) {
            uint32_t ah[2][4], al[2][4];
            uint32_t wh[4][2], wl[4][2];
#pragma unroll
            for (int i = 0; i < 2; i++) {
                LDMX4(ah[i][0], ah[i][1], ah[i][2], ah[i][3], base + aRel[i] + s * 32);
                LDMX4(al[i][0], al[i][1], al[i][2], al[i][3], base + lRel[i] + s * 32);
            }
#pragma unroll
            for (int p = 0; p < 2; p++) {
                LDMX4(wh[2 * p][0], wh[2 * p][1], wh[2 * p + 1][0], wh[2 * p + 1][1],
                      base + bRel[p] + s * 32);
                LDMX4(wl[2 * p][0], wl[2 * p][1], wl[2 * p + 1][0], wl[2 * p + 1][1],
                      base + blRel[p] + s * 32);
            }
#pragma unroll
            for (int i = 0; i < 2; i++)
#pragma unroll
                for (int j = 0; j < 4; j++) {
                    MMA16816(acc[i][j], ah[i], wh[j]);
                    MMA16816(acc[i][j], ah[i], wl[j]);
                    MMA16816(acc[i][j], al[i], wh[j]);
                }
        }
    }
    __syncthreads();  // all compute done before reusing smem for epilogue

    // ---- epilogue: stage 128x64 fp32 tile in smem (stride 68 floats) ----
    float* otile = (float*)smem;
#pragma unroll
    for (int i = 0; i < 2; i++)
#pragma unroll
        for (int j = 0; j < 4; j++) {
            int r0 = warp_m * 32 + i * 16 + (lane >> 2);
            int c0 = warp_n * 32 + j * 8 + (lane & 3) * 2;
            *(float2*)(otile + r0 * 68 + c0)       = make_float2(acc[i][j][0], acc[i][j][1]);
            *(float2*)(otile + (r0 + 8) * 68 + c0) = make_float2(acc[i][j][2], acc[i][j][3]);
        }
    __syncthreads();

#pragma unroll
    for (int it = 0; it < 8; it++) {
        int idx = tid + it * 256;
        int row = idx >> 4;
        int c4 = idx & 15;
        int gr = m0 + row;
        if (gr < M) {
            float4 v = *(float4*)(otile + row * 68 + c4 * 4);
            *(float4*)(C + (size_t)gr * NC + bn + c4 * 4) = v;
        }
    }
}

// ---------------------------------------------------------------------------
// Aggregation: out[v] = dinv[v]*(sum dinv[src]*h[src] + dinv[v]*h[v]) + bias
// One warp/node; neighbor loop unrolled x4 for memory-level parallelism.
// ---------------------------------------------------------------------------
__global__ void k_agg256(const float* __restrict__ h, const float* __restrict__ bias,
                         float* __restrict__ out, int stats)
{
    int warp = threadIdx.x >> 5, lane = threadIdx.x & 31;
    int v = blockIdx.x * 8 + warp;

    float4 a0 = make_float4(0.f, 0.f, 0.f, 0.f);
    float4 a1 = make_float4(0.f, 0.f, 0.f, 0.f);

    int beg = g_rowptr[v], end = g_rowptr[v + 1];
    int nb = end - beg;
    for (int base = 0; base < nb; base += 32) {
        int rem = nb - base;
        int cnt = rem < 32 ? rem : 32;
        int idx = base + lane;
        int sl = (idx < nb) ? g_csrsrc[beg + idx] : 0;
        float wl = (idx < nb) ? g_dinv[sl] : 0.f;
        int j = 0;
        for (; j + 4 <= cnt; j += 4) {
            int   s0 = __shfl_sync(0xffffffffu, sl, j);
            int   s1 = __shfl_sync(0xffffffffu, sl, j + 1);
            int   s2 = __shfl_sync(0xffffffffu, sl, j + 2);
            int   s3 = __shfl_sync(0xffffffffu, sl, j + 3);
            float w0 = __shfl_sync(0xffffffffu, wl, j);
            float w1 = __shfl_sync(0xffffffffu, wl, j + 1);
            float w2 = __shfl_sync(0xffffffffu, wl, j + 2);
            float w3 = __shfl_sync(0xffffffffu, wl, j + 3);
            const float4* r0 = (const float4*)(h + (size_t)s0 * 256);
            const float4* r1 = (const float4*)(h + (size_t)s1 * 256);
            const float4* r2 = (const float4*)(h + (size_t)s2 * 256);
            const float4* r3 = (const float4*)(h + (size_t)s3 * 256);
            float4 p0a = r0[lane], p0b = r0[lane + 32];
            float4 p1a = r1[lane], p1b = r1[lane + 32];
            float4 p2a = r2[lane], p2b = r2[lane + 32];
            float4 p3a = r3[lane], p3b = r3[lane + 32];
            a0.x += w0 * p0a.x; a0.y += w0 * p0a.y; a0.z += w0 * p0a.z; a0.w += w0 * p0a.w;
            a1.x += w0 * p0b.x; a1.y += w0 * p0b.y; a1.z += w0 * p0b.z; a1.w += w0 * p0b.w;
            a0.x += w1 * p1a.x; a0.y += w1 * p1a.y; a0.z += w1 * p1a.z; a0.w += w1 * p1a.w;
            a1.x += w1 * p1b.x; a1.y += w1 * p1b.y; a1.z += w1 * p1b.z; a1.w += w1 * p1b.w;
            a0.x += w2 * p2a.x; a0.y += w2 * p2a.y; a0.z += w2 * p2a.z; a0.w += w2 * p2a.w;
            a1.x += w2 * p2b.x; a1.y += w2 * p2b.y; a1.z += w2 * p2b.z; a1.w += w2 * p2b.w;
            a0.x += w3 * p3a.x; a0.y += w3 * p3a.y; a0.z += w3 * p3a.z; a0.w += w3 * p3a.w;
            a1.x += w3 * p3b.x; a1.y += w3 * p3b.y; a1.z += w3 * p3b.z; a1.w += w3 * p3b.w;
        }
        for (; j < cnt; j++) {
            int   s = __shfl_sync(0xffffffffu, sl, j);
            float w = __shfl_sync(0xffffffffu, wl, j);
            const float4* rr = (const float4*)(h + (size_t)s * 256);
            float4 f0 = rr[lane], f1 = rr[lane + 32];
            a0.x += w * f0.x; a0.y += w * f0.y; a0.z += w * f0.z; a0.w += w * f0.w;
            a1.x += w * f1.x; a1.y += w * f1.y; a1.z += w * f1.z; a1.w += w * f1.w;
        }
    }
    float dv = g_dinv[v];
    {
        const float4* rr = (const float4*)(h + (size_t)v * 256);
        float4 f0 = rr[lane], f1 = rr[lane + 32];
        a0.x += dv * f0.x; a0.y += dv * f0.y; a0.z += dv * f0.z; a0.w += dv * f0.w;
        a1.x += dv * f1.x; a1.y += dv * f1.y; a1.z += dv * f1.z; a1.w += dv * f1.w;
    }
    const float4* bb = (const float4*)bias;
    float4 b0 = bb[lane], b1 = bb[lane + 32];
    float4 r0, r1;
    r0.x = a0.x * dv + b0.x; r0.y = a0.y * dv + b0.y;
    r0.z = a0.z * dv + b0.z; r0.w = a0.w * dv + b0.w;
    r1.x = a1.x * dv + b1.x; r1.y = a1.y * dv + b1.y;
    r1.z = a1.z * dv + b1.z; r1.w = a1.w * dv + b1.w;

    float4* op = (float4*)(out + (size_t)v * 256);
    op[lane] = r0; op[lane + 32] = r1;

    if (stats) {
        float lsum = r0.x + r0.y + r0.z + r0.w + r1.x + r1.y + r1.z + r1.w;
        float lsq  = r0.x*r0.x + r0.y*r0.y + r0.z*r0.z + r0.w*r0.w
                   + r1.x*r1.x + r1.y*r1.y + r1.z*r1.z + r1.w*r1.w;
#pragma unroll
        for (int off = 16; off > 0; off >>= 1) {
            lsum += __shfl_down_sync(0xffffffffu, lsum, off);
            lsq  += __shfl_down_sync(0xffffffffu, lsq,  off);
        }
        __shared__ float ss[8], sq[8];
        if (lane == 0) { ss[warp] = lsum; sq[warp] = lsq; }
        __syncthreads();
        if (threadIdx.x == 0) {
            float S = 0.f, Q = 0.f;
#pragma unroll
            for (int w = 0; w < 8; w++) { S += ss[w]; Q += sq[w]; }
            atomicAdd(&g_S[0], S);
            atomicAdd(&g_S[1], Q);
        }
    }
}

__global__ void k_agg128(const float* __restrict__ h, const float* __restrict__ bias,
                         float* __restrict__ out)
{
    int warp = threadIdx.x >> 5, lane = threadIdx.x & 31;
    int v = blockIdx.x * 8 + warp;

    float4 a0 = make_float4(0.f, 0.f, 0.f, 0.f);
    int beg = g_rowptr[v], end = g_rowptr[v + 1];
    int nb = end - beg;
    for (int base = 0; base < nb; base += 32) {
        int rem = nb - base;
        int cnt = rem < 32 ? rem : 32;
        int idx = base + lane;
        int sl = (idx < nb) ? g_csrsrc[beg + idx] : 0;
        float wl = (idx < nb) ? g_dinv[sl] : 0.f;
        int j = 0;
        for (; j + 4 <= cnt; j += 4) {
            int   s0 = __shfl_sync(0xffffffffu, sl, j);
            int   s1 = __shfl_sync(0xffffffffu, sl, j + 1);
            int   s2 = __shfl_sync(0xffffffffu, sl, j + 2);
            int   s3 = __shfl_sync(0xffffffffu, sl, j + 3);
            float w0 = __shfl_sync(0xffffffffu, wl, j);
            float w1 = __shfl_sync(0xffffffffu, wl, j + 1);
            float w2 = __shfl_sync(0xffffffffu, wl, j + 2);
            float w3 = __shfl_sync(0xffffffffu, wl, j + 3);
            float4 p0 = ((const float4*)(h + (size_t)s0 * 128))[lane];
            float4 p1 = ((const float4*)(h + (size_t)s1 * 128))[lane];
            float4 p2 = ((const float4*)(h + (size_t)s2 * 128))[lane];
            float4 p3 = ((const float4*)(h + (size_t)s3 * 128))[lane];
            a0.x += w0 * p0.x; a0.y += w0 * p0.y; a0.z += w0 * p0.z; a0.w += w0 * p0.w;
            a0.x += w1 * p1.x; a0.y += w1 * p1.y; a0.z += w1 * p1.z; a0.w += w1 * p1.w;
            a0.x += w2 * p2.x; a0.y += w2 * p2.y; a0.z += w2 * p2.z; a0.w += w2 * p2.w;
            a0.x += w3 * p3.x; a0.y += w3 * p3.y; a0.z += w3 * p3.z; a0.w += w3 * p3.w;
        }
        for (; j < cnt; j++) {
            int   s = __shfl_sync(0xffffffffu, sl, j);
            float w = __shfl_sync(0xffffffffu, wl, j);
            float4 f0 = ((const float4*)(h + (size_t)s * 128))[lane];
            a0.x += w * f0.x; a0.y += w * f0.y; a0.z += w * f0.z; a0.w += w * f0.w;
        }
    }
    float dv = g_dinv[v];
    {
        float4 f0 = ((const float4*)(h + (size_t)v * 128))[lane];
        a0.x += dv * f0.x; a0.y += dv * f0.y; a0.z += dv * f0.z; a0.w += dv * f0.w;
    }
    const float4* bb = (const float4*)bias;
    float4 b0 = bb[lane];
    float4 r0;
    r0.x = a0.x * dv + b0.x; r0.y = a0.y * dv + b0.y;
    r0.z = a0.z * dv + b0.z; r0.w = a0.w * dv + b0.w;
    ((float4*)(out + (size_t)v * 128))[lane] = r0;
}

// ---------------------------------------------------------------------------
// LayerNorm apply: derives mean/invstd inline from g_S (no separate kernel),
// y = lrelu((x-mean)*invstd*gamma + beta), emitted as bf16 hi/lo for next GEMM
// ---------------------------------------------------------------------------
__global__ void k_apply(const float* __restrict__ buf,
                        const float* __restrict__ gma,
                        const float* __restrict__ bta,
                        __nv_bfloat16* __restrict__ ah,
                        __nv_bfloat16* __restrict__ al)
{
    const float cnt = (float)NN * 256.0f;
    float mean = g_S[0] / cnt;
    float var  = fmaxf(g_S[1] / cnt - mean * mean, 0.f);
    float scale = 1.0f / (sqrtf(var) + 1e-5f);

    int i4 = blockIdx.x * blockDim.x + threadIdx.x;  // NN*64 total
    int c4 = i4 & 63;
    float4 g = ((const float4*)gma)[c4];
    float4 b = ((const float4*)bta)[c4];
    float4 v = ((const float4*)buf)[i4];
    v.x = (v.x - mean) * scale * g.x + b.x;
    v.y = (v.y - mean) * scale * g.y + b.y;
    v.z = (v.z - mean) * scale * g.z + b.z;
    v.w = (v.w - mean) * scale * g.w + b.w;
    v.x = v.x > 0.f ? v.x : 0.01f * v.x;
    v.y = v.y > 0.f ? v.y : 0.01f * v.y;
    v.z = v.z > 0.f ? v.z : 0.01f * v.z;
    v.w = v.w > 0.f ? v.w : 0.01f * v.w;
    uint2 hv, lv;
    split4(v, hv, lv);
    ((uint2*)ah)[i4] = hv;
    ((uint2*)al)[i4] = lv;
}

// ---------------------------------------------------------------------------
// Host launcher
// ---------------------------------------------------------------------------
extern "C" void kernel_launch(void* const* d_in, const int* in_sizes, int n_in,
                              void* d_out, int out_size)
{
    const float* x   = (const float*)d_in[0];
    const int*   ei  = (const int*)d_in[1];
    const int*   src = ei;
    const int*   dst = ei + NE;
    const float* W1 = (const float*)d_in[2];
    const float* b1 = (const float*)d_in[3];
    const float* g1 = (const float*)d_in[4];
    const float* e1 = (const float*)d_in[5];
    const float* W2 = (const float*)d_in[6];
    const float* b2 = (const float*)d_in[7];
    const float* g2 = (const float*)d_in[8];
    const float* e2 = (const float*)d_in[9];
    const float* W3 = (const float*)d_in[10];
    const float* b3 = (const float*)d_in[11];
    const float* g3 = (const float*)d_in[12];
    const float* e3 = (const float*)d_in[13];
    const float* W4 = (const float*)d_in[14];
    const float* b4 = (const float*)d_in[15];
    float* out = (float*)d_out;

    float *bufA = nullptr, *bufB = nullptr;
    cudaGetSymbolAddress((void**)&bufA, g_bufA);
    cudaGetSymbolAddress((void**)&bufB, g_bufB);
    __nv_bfloat16 *ah, *al;
    cudaGetSymbolAddress((void**)&ah, g_ah);
    cudaGetSymbolAddress((void**)&al, g_al);
    __nv_bfloat16 *w1h, *w1l, *w2h, *w2l, *w3h, *w3l, *w4h, *w4l;
    cudaGetSymbolAddress((void**)&w1h, g_w1h); cudaGetSymbolAddress((void**)&w1l, g_w1l);
    cudaGetSymbolAddress((void**)&w2h, g_w2h); cudaGetSymbolAddress((void**)&w2l, g_w2l);
    cudaGetSymbolAddress((void**)&w3h, g_w3h); cudaGetSymbolAddress((void**)&w3l, g_w3l);
    cudaGetSymbolAddress((void**)&w4h, g_w4h); cudaGetSymbolAddress((void**)&w4l, g_w4l);

    static bool attr_done = false;
    if (!attr_done) {
        cudaFuncSetAttribute(k_gemm_mma<256>, cudaFuncAttributeMaxDynamicSharedMemorySize, GEMM_SMEM);
        cudaFuncSetAttribute(k_gemm_mma<128>, cudaFuncAttributeMaxDynamicSharedMemorySize, GEMM_SMEM);
        attr_done = true;
    }

    const int T = 256;
    // ---- CSR build ----
    k_zero_counts<<<(NN + T - 1) / T, T>>>();
    k_degree<<<(NE + T - 1) / T, T>>>(dst);
    k_dinv<<<(NN + T - 1) / T, T>>>();
    k_scan1<<<NBLK, 1024>>>();
    k_scan2<<<1, 1>>>();
    k_scan3<<<(NN + T - 1) / T, T>>>();
    k_scatter<<<(NE + T - 1) / T, T>>>(src, dst);

    // ---- weight + input prep ----
    k_wprep<<<(256 * 256 + T - 1) / T, T>>>(W1, w1h, w1l, 256);
    k_wprep<<<(256 * 256 + T - 1) / T, T>>>(W2, w2h, w2l, 256);
    k_wprep<<<(256 * 256 + T - 1) / T, T>>>(W3, w3h, w3l, 256);
    k_wprep<<<(256 * 128 + T - 1) / T, T>>>(W4, w4h, w4l, 128);

    dim3 grid256(4, (NN + 127) / 128);    // x = n-block, y = m-block
    dim3 grid128(2, (NN + 127) / 128);
    int aggBlocks = NN / 8;               // 12500
    int vecBlocks = (NN * 64) / T;        // 25000

    k_xconv<<<vecBlocks, T>>>(x, ah, al);

    // ---- layer 1 ----
    k_gemm_mma<256><<<grid256, 256, GEMM_SMEM>>>(ah, al, w1h, w1l, bufA, NN);
    k_agg256<<<aggBlocks, 256>>>(bufA, b1, bufB, 1);
    k_apply<<<vecBlocks, T>>>(bufB, g1, e1, ah, al);

    // ---- layer 2 ----
    k_gemm_mma<256><<<grid256, 256, GEMM_SMEM>>>(ah, al, w2h, w2l, bufA, NN);
    k_agg256<<<aggBlocks, 256>>>(bufA, b2, bufB, 1);
    k_apply<<<vecBlocks, T>>>(bufB, g2, e2, ah, al);

    // ---- layer 3 ----
    k_gemm_mma<256><<<grid256, 256, GEMM_SMEM>>>(ah, al, w3h, w3l, bufA, NN);
    k_agg256<<<aggBlocks, 256>>>(bufA, b3, bufB, 1);
    k_apply<<<vecBlocks, T>>>(bufB, g3, e3, ah, al);

    // ---- layer 4 (D=128, no LN) ----
    k_gemm_mma<128><<<grid128, 256, GEMM_SMEM>>>(ah, al, w4h, w4l, bufA, NN);
    k_agg128<<<aggBlocks, 256>>>(bufA, b4, out);
}